// round 7
// baseline (speedup 1.0000x reference)
#include <cuda_runtime.h>
#include <cstdint>

#define NB 64
#define NC 2
#define LSIG 131072
#define K 4
#define NCH (NB*NC)
#define THREADS 512
#define SUB 128                 /* samples per chunk (scan element pair-half) */
#define LEVELS 9                /* log2(THREADS) block scan over pair-aggregates */
#define TILE 16                 /* samples per smem tile */
#define NTILES (SUB/TILE)       /* 8 */
#define RPITCH 20               /* floats per smem row (16B aligned, swizzle-friendly) */
#define ARR (THREADS*RPITCH)    /* floats per array (Lo or Hi) = 10240 */
#define BUFF (2*ARR)            /* floats per double-buffer slot = 20480 */

typedef unsigned long long u64;

__device__ __forceinline__ u64 pk2(float lo, float hi) {
    u64 r; asm("mov.b64 %0,{%1,%2};" : "=l"(r) : "f"(lo), "f"(hi)); return r;
}
__device__ __forceinline__ void upk2(u64 v, float& lo, float& hi) {
    asm("mov.b64 {%0,%1},%2;" : "=f"(lo), "=f"(hi) : "l"(v));
}
__device__ __forceinline__ u64 fma2(u64 a, u64 b, u64 c) {
    u64 d; asm("fma.rn.f32x2 %0,%1,%2,%3;" : "=l"(d) : "l"(a), "l"(b), "l"(c)); return d;
}
__device__ __forceinline__ u64 mul2(u64 a, u64 b) {
    u64 d; asm("mul.rn.f32x2 %0,%1,%2;" : "=l"(d) : "l"(a), "l"(b)); return d;
}
__device__ __forceinline__ void cp16(uint32_t dst, const void* src) {
    asm volatile("cp.async.cg.shared.global [%0], [%1], 16;" :: "r"(dst), "l"(src));
}
__device__ __forceinline__ void cp_commit() {
    asm volatile("cp.async.commit_group;");
}
template<int N> __device__ __forceinline__ void cp_wait() {
    asm volatile("cp.async.wait_group %0;" :: "n"(N));
}

struct Coef { float b0[K], b1[K], b2[K], na1[K], na2[K]; };
struct Coef2 { u64 b0[K], b1[K], b2[K], na1[K], na2[K]; };

__device__ __forceinline__ float cascade_step(float u, float s1[K], float s2[K], const Coef& cf) {
#pragma unroll
    for (int k = 0; k < K; ++k) {
        float y = fmaf(cf.b0[k], u, s1[k]);
        s1[k] = fmaf(cf.b1[k], u, fmaf(cf.na1[k], y, s2[k]));
        s2[k] = fmaf(cf.b2[k], u, cf.na2[k] * y);
        u = y;
    }
    return u;
}

__device__ __forceinline__ u64 cascade_step2(u64 u, u64 s1[K], u64 s2[K], const Coef2& cf) {
#pragma unroll
    for (int k = 0; k < K; ++k) {
        u64 y = fma2(cf.b0[k], u, s1[k]);
        s1[k] = fma2(cf.b1[k], u, fma2(cf.na1[k], y, s2[k]));
        s2[k] = fma2(cf.b2[k], u, mul2(cf.na2[k], y));
        u = y;
    }
    return u;
}

extern __shared__ float dyn_smem[];   // [2][2][THREADS][RPITCH] double-buffered Lo/Hi

// issue one tile's cp.async (4096 x 16B), swizzled destination
__device__ __forceinline__ void prefetch_tile(const float* __restrict__ xch,
                                              uint32_t sbase, int tile, int b, int tid)
{
    const float* src0 = xch + tile * TILE;
    uint32_t dstbase = sbase + (uint32_t)(b * BUFF) * 4u;
#pragma unroll
    for (int it = 0; it < 8; ++it) {
        int f = tid + it * THREADS;        // 0..4095
        int c = f >> 2;                    // chunk 0..1023
        int w = f & 3;                     // float4 group within tile
        int r = c >> 1;
        int a = c & 1;
        uint32_t off = (uint32_t)(a * ARR + r * RPITCH + ((w ^ ((r >> 3) & 3)) << 2)) * 4u;
        cp16(dstbase + off, src0 + (size_t)c * SUB + w * 4);
    }
    cp_commit();
}

__global__ void __launch_bounds__(THREADS, 1)
iir_cascade_kernel(const float* __restrict__ x,
                   const float* __restrict__ Bs,
                   const float* __restrict__ As,
                   float* __restrict__ yout)
{
    __shared__ float S[THREADS][8];         // pair-aggregate scan array
    __shared__ float Mats[LEVELS][8][8];    // A^(256 * 2^l)
    __shared__ float A128[8][8];            // A^128 (pair combine)
    __shared__ float P[8][8];               // running power of A

    const int ch  = blockIdx.x;
    const int tid = threadIdx.x;
    const uint32_t sbase = (uint32_t)__cvta_generic_to_shared(dyn_smem);

    const float* __restrict__ xch = x + (size_t)ch * LSIG;
    float* __restrict__ ych = yout + (size_t)ch * LSIG;

    // kick off the first two tile loads before any setup work
    prefetch_tile(xch, sbase, 0, 0, tid);
    prefetch_tile(xch, sbase, 1, 1, tid);

    // ---- load + normalize coefficients ----
    Coef cf;
    {
        const float* bs = Bs + (size_t)ch * K * 3;
        const float* as = As + (size_t)ch * K * 3;
#pragma unroll
        for (int k = 0; k < K; ++k) {
            float inv = 1.0f / as[k * 3 + 0];
            cf.b0[k]  = bs[k * 3 + 0] * inv;
            cf.b1[k]  = bs[k * 3 + 1] * inv;
            cf.b2[k]  = bs[k * 3 + 2] * inv;
            cf.na1[k] = -(as[k * 3 + 1] * inv);
            cf.na2[k] = -(as[k * 3 + 2] * inv);
        }
    }

    // ---- build state matrix A ----
    if (tid < 8) {
        float t1[K], t2[K];
#pragma unroll
        for (int k = 0; k < K; ++k) {
            t1[k] = (2 * k     == tid) ? 1.f : 0.f;
            t2[k] = (2 * k + 1 == tid) ? 1.f : 0.f;
        }
        cascade_step(0.f, t1, t2, cf);
#pragma unroll
        for (int k = 0; k < K; ++k) {
            P[2 * k][tid]     = t1[k];
            P[2 * k + 1][tid] = t2[k];
        }
    }

    // ---- broadcast-pack coefficients ----
    Coef2 c2;
#pragma unroll
    for (int k = 0; k < K; ++k) {
        c2.b0[k]  = pk2(cf.b0[k],  cf.b0[k]);
        c2.b1[k]  = pk2(cf.b1[k],  cf.b1[k]);
        c2.b2[k]  = pk2(cf.b2[k],  cf.b2[k]);
        c2.na1[k] = pk2(cf.na1[k], cf.na1[k]);
        c2.na2[k] = pk2(cf.na2[k], cf.na2[k]);
    }

    // per-thread swizzled row pointers (4 group pointers per array per buffer)
    const int sw = (tid >> 3) & 3;
    const float* lg[2][4];
    const float* hg[2][4];
#pragma unroll
    for (int b = 0; b < 2; ++b) {
#pragma unroll
        for (int g = 0; g < 4; ++g) {
            lg[b][g] = dyn_smem + b * BUFF + 0 * ARR + tid * RPITCH + ((g ^ sw) << 2);
            hg[b][g] = dyn_smem + b * BUFF + 1 * ARR + tid * RPITCH + ((g ^ sw) << 2);
        }
    }

    // ================= Pass A: zero-init packed run, pipelined tiles ==========
    u64 s1[K] = {0, 0, 0, 0};
    u64 s2[K] = {0, 0, 0, 0};
#pragma unroll 1
    for (int tile = 0; tile < NTILES; ++tile) {
        const int b = tile & 1;
        cp_wait<1>();
        __syncthreads();
#pragma unroll
        for (int j = 0; j < TILE; ++j) {
            float xl = lg[b][j >> 2][j & 3];
            float xh = hg[b][j >> 2][j & 3];
            cascade_step2(pk2(xl, xh), s1, s2, c2);
        }
        __syncthreads();   // everyone done reading buffer b
        if (tile + 2 < NTILES) prefetch_tile(xch, sbase, tile + 2, b, tid);
        else cp_commit();  // keep group accounting uniform
    }
    float sc_lo[8], sc_hi[8];
#pragma unroll
    for (int k = 0; k < K; ++k) {
        upk2(s1[k], sc_lo[2 * k],     sc_hi[2 * k]);
        upk2(s2[k], sc_lo[2 * k + 1], sc_hi[2 * k + 1]);
    }

    // start pass-B tile loads now; they overlap the whole scan section
    prefetch_tile(xch, sbase, 0, 0, tid);
    prefetch_tile(xch, sbase, 1, 1, tid);

    __syncthreads();   // P visible to squaring warps

    // ---- repeated squaring (warps 0-1): A128 = A^128, Mats[l] = A^(256*2^l) ----
    if (tid < 64) {
        const int r = tid >> 3, c = tid & 7;
        for (int it = 1; it <= 16; ++it) {
            float val = 0.f;
#pragma unroll
            for (int kk = 0; kk < 8; ++kk) val = fmaf(P[r][kk], P[kk][c], val);
            asm volatile("bar.sync 1, 64;" ::: "memory");
            P[r][c] = val;
            if (it == 7) A128[r][c] = val;
            if (it >= 8) Mats[it - 8][r][c] = val;
            asm volatile("bar.sync 1, 64;" ::: "memory");
        }
    }
    __syncthreads();

    // ---- local pair combine: agg = A128 * sc_lo + sc_hi ----
    float agg[8];
#pragma unroll
    for (int r = 0; r < 8; ++r) {
        float acc = sc_hi[r];
#pragma unroll
        for (int c = 0; c < 8; ++c) acc = fmaf(A128[r][c], sc_lo[c], acc);
        agg[r] = acc;
        S[tid][r] = acc;
    }
    __syncthreads();

    // ---- Kogge-Stone affine scan over 512 pair-aggregates ----
    for (int l = 0; l < LEVELS; ++l) {
        int d = 1 << l;
        float t[8];
        bool act = (tid >= d);
        if (act) {
#pragma unroll
            for (int i = 0; i < 8; ++i) t[i] = S[tid - d][i];
        }
        __syncthreads();
        if (act) {
#pragma unroll
            for (int r = 0; r < 8; ++r) {
                float acc = agg[r];
#pragma unroll
                for (int c = 0; c < 8; ++c) acc = fmaf(Mats[l][r][c], t[c], acc);
                agg[r] = acc;
            }
#pragma unroll
            for (int i = 0; i < 8; ++i) S[tid][i] = agg[i];
        }
        __syncthreads();
    }

    // ---- initial states ----
    float init0[8], init1[8];
    if (tid == 0) {
#pragma unroll
        for (int i = 0; i < 8; ++i) init0[i] = 0.f;
    } else {
#pragma unroll
        for (int i = 0; i < 8; ++i) init0[i] = S[tid - 1][i];
    }
#pragma unroll
    for (int r = 0; r < 8; ++r) {
        float acc = sc_lo[r];
#pragma unroll
        for (int c = 0; c < 8; ++c) acc = fmaf(A128[r][c], init0[c], acc);
        init1[r] = acc;
    }

    // ================= Pass B: rerun from corrected states, pipelined ========
    u64 r1[K], r2[K];
#pragma unroll
    for (int k = 0; k < K; ++k) {
        r1[k] = pk2(init0[2 * k],     init1[2 * k]);
        r2[k] = pk2(init0[2 * k + 1], init1[2 * k + 1]);
    }

#pragma unroll 1
    for (int tile = 0; tile < NTILES; ++tile) {
        const int b = tile & 1;
        cp_wait<1>();
        __syncthreads();
        // compute; overwrite own rows in place with outputs
#pragma unroll
        for (int j = 0; j < TILE; ++j) {
            float xl = lg[b][j >> 2][j & 3];
            float xh = hg[b][j >> 2][j & 3];
            u64 y = cascade_step2(pk2(xl, xh), r1, r2, c2);
            float yl, yh;
            upk2(y, yl, yh);
            const_cast<float*>(lg[b][j >> 2])[j & 3] = yl;
            const_cast<float*>(hg[b][j >> 2])[j & 3] = yh;
        }
        __syncthreads();   // outputs visible block-wide
        // coalesced drain: LDS.128 -> STG.128
#pragma unroll
        for (int it = 0; it < 8; ++it) {
            int f = tid + it * THREADS;
            int c = f >> 2, w = f & 3;
            int r = c >> 1, a = c & 1;
            const float4 v = *reinterpret_cast<const float4*>(
                dyn_smem + b * BUFF + a * ARR + r * RPITCH + ((w ^ ((r >> 3) & 3)) << 2));
            *reinterpret_cast<float4*>(ych + (size_t)c * SUB + tile * TILE + w * 4) = v;
        }
        __syncthreads();   // all reads of buffer b done before overwrite
        if (tile + 2 < NTILES) prefetch_tile(xch, sbase, tile + 2, b, tid);
        else cp_commit();
    }
}

extern "C" void kernel_launch(void* const* d_in, const int* in_sizes, int n_in,
                              void* d_out, int out_size)
{
    const float* x  = (const float*)d_in[0];   // (B, C, L) float32
    const float* Bs = (const float*)d_in[1];   // (B, C, K, 3) float32
    const float* As = (const float*)d_in[2];   // (B, C, K, 3) float32
    float* y = (float*)d_out;                  // (B, C, L) float32

    const int dyn_bytes = 2 * BUFF * sizeof(float);   // 163840
    static bool attr_set = false;
    if (!attr_set) {
        cudaFuncSetAttribute(iir_cascade_kernel,
                             cudaFuncAttributeMaxDynamicSharedMemorySize, dyn_bytes);
        attr_set = true;
    }
    iir_cascade_kernel<<<NCH, THREADS, dyn_bytes>>>(x, Bs, As, y);
}

// round 9
// speedup vs baseline: 1.0641x; 1.0641x over previous
#include <cuda_runtime.h>
#include <cstdint>

#define NB 64
#define NC 2
#define LSIG 131072
#define K 4
#define NCH (NB*NC)
#define THREADS 512
#define CHUNK 64                 /* samples per chunk */
#define NCHUNK 2048              /* chunks per channel */
#define LEVELS 9                 /* block scan levels over 512 thread-aggregates */
#define TILE 16                  /* samples staged per chunk per tile */
#define NTILES (CHUNK/TILE)      /* 4 */
#define PITCH 17                 /* floats per staged row */
#define SEGSZ (512*PITCH + 33)   /* 8737 floats per segment (pad shifts banks) */

typedef unsigned long long u64;

__device__ __forceinline__ u64 pk2(float lo, float hi) {
    u64 r; asm("mov.b64 %0,{%1,%2};" : "=l"(r) : "f"(lo), "f"(hi)); return r;
}
__device__ __forceinline__ void upk2(u64 v, float& lo, float& hi) {
    asm("mov.b64 {%0,%1},%2;" : "=f"(lo), "=f"(hi) : "l"(v));
}
__device__ __forceinline__ u64 fma2(u64 a, u64 b, u64 c) {
    u64 d; asm("fma.rn.f32x2 %0,%1,%2,%3;" : "=l"(d) : "l"(a), "l"(b), "l"(c)); return d;
}
__device__ __forceinline__ u64 mul2(u64 a, u64 b) {
    u64 d; asm("mul.rn.f32x2 %0,%1,%2;" : "=l"(d) : "l"(a), "l"(b)); return d;
}

struct Coef { float b0[K], b1[K], b2[K], na1[K], na2[K]; };
struct Coef2 { u64 b0[K], b1[K], b2[K], na1[K], na2[K]; };

__device__ __forceinline__ float cascade_step(float u, float s1[K], float s2[K], const Coef& cf) {
#pragma unroll
    for (int k = 0; k < K; ++k) {
        float y = fmaf(cf.b0[k], u, s1[k]);
        s1[k] = fmaf(cf.b1[k], u, fmaf(cf.na1[k], y, s2[k]));
        s2[k] = fmaf(cf.b2[k], u, cf.na2[k] * y);
        u = y;
    }
    return u;
}

__device__ __forceinline__ u64 cascade_step2(u64 u, u64 s1[K], u64 s2[K], const Coef2& cf) {
#pragma unroll
    for (int k = 0; k < K; ++k) {
        u64 y = fma2(cf.b0[k], u, s1[k]);
        s1[k] = fma2(cf.b1[k], u, fma2(cf.na1[k], y, s2[k]));
        s2[k] = fma2(cf.b2[k], u, mul2(cf.na2[k], y));
        u = y;
    }
    return u;
}

extern __shared__ float dyn_smem[];   // 4 segments * SEGSZ floats (staging + scratch)

// cooperative staged load of one tile (16 samples of every chunk)
__device__ __forceinline__ void load_tile(const float* __restrict__ xch, int tile, int tid)
{
#pragma unroll
    for (int it = 0; it < 16; ++it) {
        int f = tid + it * THREADS;            // 0..8191
        int c = f >> 2;                        // chunk 0..2047
        int w = f & 3;                         // float4 group within tile
        float4 v = *reinterpret_cast<const float4*>(xch + (size_t)c * CHUNK + tile * TILE + w * 4);
        float* row = dyn_smem + (c & 3) * SEGSZ + (c >> 2) * PITCH + w * 4;
        row[0] = v.x; row[1] = v.y; row[2] = v.z; row[3] = v.w;
    }
}

__global__ void __launch_bounds__(THREADS, 1)
iir_cascade_kernel(const float* __restrict__ x,
                   const float* __restrict__ Bs,
                   const float* __restrict__ As,
                   float* __restrict__ yout)
{
    __shared__ float S[THREADS][8];         // thread-aggregate scan array
    __shared__ float Mats[LEVELS][8][8];    // A^(256 * 2^l), l=0..8
    __shared__ float A64[8][8];             // A^64 (intra-thread combine)
    __shared__ float P[8][8];               // running power of A

    const int ch  = blockIdx.x;
    const int tid = threadIdx.x;

    const float* __restrict__ xch = x + (size_t)ch * LSIG;
    float* __restrict__ ych = yout + (size_t)ch * LSIG;

    // ---- load + normalize coefficients ----
    Coef cf;
    {
        const float* bs = Bs + (size_t)ch * K * 3;
        const float* as = As + (size_t)ch * K * 3;
#pragma unroll
        for (int k = 0; k < K; ++k) {
            float inv = 1.0f / as[k * 3 + 0];
            cf.b0[k]  = bs[k * 3 + 0] * inv;
            cf.b1[k]  = bs[k * 3 + 1] * inv;
            cf.b2[k]  = bs[k * 3 + 2] * inv;
            cf.na1[k] = -(as[k * 3 + 1] * inv);
            cf.na2[k] = -(as[k * 3 + 2] * inv);
        }
    }

    // ---- build state matrix A (column i = one zero-input step from e_i) ----
    if (tid < 8) {
        float t1[K], t2[K];
#pragma unroll
        for (int k = 0; k < K; ++k) {
            t1[k] = (2 * k     == tid) ? 1.f : 0.f;
            t2[k] = (2 * k + 1 == tid) ? 1.f : 0.f;
        }
        cascade_step(0.f, t1, t2, cf);
#pragma unroll
        for (int k = 0; k < K; ++k) {
            P[2 * k][tid]     = t1[k];
            P[2 * k + 1][tid] = t2[k];
        }
    }

    // ---- broadcast-pack coefficients for f32x2 ----
    Coef2 c2;
#pragma unroll
    for (int k = 0; k < K; ++k) {
        c2.b0[k]  = pk2(cf.b0[k],  cf.b0[k]);
        c2.b1[k]  = pk2(cf.b1[k],  cf.b1[k]);
        c2.b2[k]  = pk2(cf.b2[k],  cf.b2[k]);
        c2.na1[k] = pk2(cf.na1[k], cf.na1[k]);
        c2.na2[k] = pk2(cf.na2[k], cf.na2[k]);
    }

    // per-thread row pointers: stream A = chunks 4t,4t+1 ; stream B = 4t+2,4t+3
    const float* rA0 = dyn_smem + 0 * SEGSZ + tid * PITCH;
    const float* rA1 = dyn_smem + 1 * SEGSZ + tid * PITCH;
    const float* rB0 = dyn_smem + 2 * SEGSZ + tid * PITCH;
    const float* rB1 = dyn_smem + 3 * SEGSZ + tid * PITCH;

    // ================= Pass A: zero-init run, 2 packed streams ================
    u64 sA1[K] = {0,0,0,0}, sA2[K] = {0,0,0,0};
    u64 sB1[K] = {0,0,0,0}, sB2[K] = {0,0,0,0};
#pragma unroll 1
    for (int tile = 0; tile < NTILES; ++tile) {
        __syncthreads();                 // prior tile's reads complete
        load_tile(xch, tile, tid);
        __syncthreads();
#pragma unroll
        for (int j = 0; j < TILE; ++j) {
            float a0 = rA0[j], a1 = rA1[j], b0 = rB0[j], b1 = rB1[j];
            cascade_step2(pk2(a0, a1), sA1, sA2, c2);
            cascade_step2(pk2(b0, b1), sB1, sB2, c2);
        }
    }

    // unpack the 4 zero-init chunk states
    float w0[8], w1[8], w2[8], w3[8];
#pragma unroll
    for (int k = 0; k < K; ++k) {
        upk2(sA1[k], w0[2*k],   w1[2*k]);
        upk2(sA2[k], w0[2*k+1], w1[2*k+1]);
        upk2(sB1[k], w2[2*k],   w3[2*k]);
        upk2(sB2[k], w2[2*k+1], w3[2*k+1]);
    }

    __syncthreads();   // pass-A staging reads done; P visible to squaring warps

    // stash w0..w2 in staging smem (frees registers across the scan)
    {
        float* st = dyn_smem + tid * 24;
#pragma unroll
        for (int i = 0; i < 8; ++i) { st[i] = w0[i]; st[8+i] = w1[i]; st[16+i] = w2[i]; }
    }

    // ---- repeated squaring (warps 0-1): A64 = A^(2^6); Mats[l] = A^(2^(8+l)) ----
    if (tid < 64) {
        const int r = tid >> 3, c = tid & 7;
        for (int it = 1; it <= 16; ++it) {
            float val = 0.f;
#pragma unroll
            for (int kk = 0; kk < 8; ++kk) val = fmaf(P[r][kk], P[kk][c], val);
            asm volatile("bar.sync 1, 64;" ::: "memory");
            P[r][c] = val;
            if (it == 6) A64[r][c] = val;
            if (it >= 8) Mats[it - 8][r][c] = val;
            asm volatile("bar.sync 1, 64;" ::: "memory");
        }
    }
    __syncthreads();   // A64 / Mats / stash visible

    // ---- thread aggregate over its 4 chunks: agg = A64*(A64*(A64*w0+w1)+w2)+w3 ----
    float agg[8];
    {
        float t1v[8], t2v[8];
#pragma unroll
        for (int r = 0; r < 8; ++r) {
            float acc = w1[r];
#pragma unroll
            for (int c = 0; c < 8; ++c) acc = fmaf(A64[r][c], w0[c], acc);
            t1v[r] = acc;
        }
#pragma unroll
        for (int r = 0; r < 8; ++r) {
            float acc = w2[r];
#pragma unroll
            for (int c = 0; c < 8; ++c) acc = fmaf(A64[r][c], t1v[c], acc);
            t2v[r] = acc;
        }
#pragma unroll
        for (int r = 0; r < 8; ++r) {
            float acc = w3[r];
#pragma unroll
            for (int c = 0; c < 8; ++c) acc = fmaf(A64[r][c], t2v[c], acc);
            agg[r] = acc;
            S[tid][r] = acc;
        }
    }
    __syncthreads();

    // ---- Kogge-Stone affine scan over 512 thread-aggregates ----
    for (int l = 0; l < LEVELS; ++l) {
        int d = 1 << l;
        float t[8];
        bool act = (tid >= d);
        if (act) {
#pragma unroll
            for (int i = 0; i < 8; ++i) t[i] = S[tid - d][i];
        }
        __syncthreads();
        if (act) {
#pragma unroll
            for (int r = 0; r < 8; ++r) {
                float acc = agg[r];
#pragma unroll
                for (int c = 0; c < 8; ++c) acc = fmaf(Mats[l][r][c], t[c], acc);
                agg[r] = acc;
            }
#pragma unroll
            for (int i = 0; i < 8; ++i) S[tid][i] = agg[i];
        }
        __syncthreads();
    }

    // ---- per-chunk initial states I0..I3 ----
    float I0[8], I1[8], I2[8], I3[8];
    if (tid == 0) {
#pragma unroll
        for (int i = 0; i < 8; ++i) I0[i] = 0.f;
    } else {
#pragma unroll
        for (int i = 0; i < 8; ++i) I0[i] = S[tid - 1][i];
    }
    {
        const float* st = dyn_smem + tid * 24;
#pragma unroll
        for (int r = 0; r < 8; ++r) {
            float acc = st[r];                      // w0
#pragma unroll
            for (int c = 0; c < 8; ++c) acc = fmaf(A64[r][c], I0[c], acc);
            I1[r] = acc;
        }
#pragma unroll
        for (int r = 0; r < 8; ++r) {
            float acc = st[8 + r];                  // w1
#pragma unroll
            for (int c = 0; c < 8; ++c) acc = fmaf(A64[r][c], I1[c], acc);
            I2[r] = acc;
        }
#pragma unroll
        for (int r = 0; r < 8; ++r) {
            float acc = st[16 + r];                 // w2
#pragma unroll
            for (int c = 0; c < 8; ++c) acc = fmaf(A64[r][c], I2[c], acc);
            I3[r] = acc;
        }
    }

    // ================= Pass B: rerun from corrected states ====================
#pragma unroll
    for (int k = 0; k < K; ++k) {
        sA1[k] = pk2(I0[2*k],   I1[2*k]);
        sA2[k] = pk2(I0[2*k+1], I1[2*k+1]);
        sB1[k] = pk2(I2[2*k],   I3[2*k]);
        sB2[k] = pk2(I2[2*k+1], I3[2*k+1]);
    }

#pragma unroll 1
    for (int tile = 0; tile < NTILES; ++tile) {
        __syncthreads();                 // prior drain reads / stash reads done
        load_tile(xch, tile, tid);
        __syncthreads();
        // compute; overwrite own rows in place with outputs
#pragma unroll
        for (int j = 0; j < TILE; ++j) {
            float a0 = rA0[j], a1 = rA1[j], b0 = rB0[j], b1 = rB1[j];
            u64 ya = cascade_step2(pk2(a0, a1), sA1, sA2, c2);
            u64 yb = cascade_step2(pk2(b0, b1), sB1, sB2, c2);
            float o0, o1, o2, o3;
            upk2(ya, o0, o1);
            upk2(yb, o2, o3);
            const_cast<float*>(rA0)[j] = o0;
            const_cast<float*>(rA1)[j] = o1;
            const_cast<float*>(rB0)[j] = o2;
            const_cast<float*>(rB1)[j] = o3;
        }
        __syncthreads();
        // coalesced drain: scalar LDS -> STG.128
#pragma unroll
        for (int it = 0; it < 16; ++it) {
            int f = tid + it * THREADS;
            int c = f >> 2, w = f & 3;
            const float* row = dyn_smem + (c & 3) * SEGSZ + (c >> 2) * PITCH + w * 4;
            float4 v;
            v.x = row[0]; v.y = row[1]; v.z = row[2]; v.w = row[3];
            *reinterpret_cast<float4*>(ych + (size_t)c * CHUNK + tile * TILE + w * 4) = v;
        }
    }
}

extern "C" void kernel_launch(void* const* d_in, const int* in_sizes, int n_in,
                              void* d_out, int out_size)
{
    const float* x  = (const float*)d_in[0];   // (B, C, L) float32
    const float* Bs = (const float*)d_in[1];   // (B, C, K, 3) float32
    const float* As = (const float*)d_in[2];   // (B, C, K, 3) float32
    float* y = (float*)d_out;                  // (B, C, L) float32

    const int dyn_bytes = 4 * SEGSZ * sizeof(float);   // 139,792 B
    static bool attr_set = false;
    if (!attr_set) {
        cudaFuncSetAttribute(iir_cascade_kernel,
                             cudaFuncAttributeMaxDynamicSharedMemorySize, dyn_bytes);
        attr_set = true;
    }
    iir_cascade_kernel<<<NCH, THREADS, dyn_bytes>>>(x, Bs, As, y);
}

// round 14
// speedup vs baseline: 1.2094x; 1.1366x over previous
#include <cuda_runtime.h>
#include <cstdint>

#define NB 64
#define NC 2
#define LSIG 131072
#define K 4
#define NCH (NB*NC)
#define THREADS 512
#define CHUNK 128                /* samples per chunk; 1024 chunks; pair per thread */
#define LEVELS 9
#define TILE 32                  /* samples per chunk staged per tile */
#define NTILES (CHUNK/TILE)      /* 4 */
#define ROW 66                   /* floats per smem row: 32 interleaved pairs + pad */

typedef unsigned long long u64;

__device__ __forceinline__ void upk2(u64 v, float& lo, float& hi) {
    asm("mov.b64 {%0,%1},%2;" : "=f"(lo), "=f"(hi) : "l"(v));
}
__device__ __forceinline__ u64 pk2(float lo, float hi) {
    u64 r; asm("mov.b64 %0,{%1,%2};" : "=l"(r) : "f"(lo), "f"(hi)); return r;
}
__device__ __forceinline__ u64 fma2(u64 a, u64 b, u64 c) {
    u64 d; asm("fma.rn.f32x2 %0,%1,%2,%3;" : "=l"(d) : "l"(a), "l"(b), "l"(c)); return d;
}
__device__ __forceinline__ u64 mul2(u64 a, u64 b) {
    u64 d; asm("mul.rn.f32x2 %0,%1,%2;" : "=l"(d) : "l"(a), "l"(b)); return d;
}

struct Coef { float b0[K], b1[K], b2[K], na1[K], na2[K]; };
struct Coef2 { u64 b0[K], b1[K], b2[K], na1[K], na2[K]; };

__device__ __forceinline__ float cascade_step(float u, float s1[K], float s2[K], const Coef& cf) {
#pragma unroll
    for (int k = 0; k < K; ++k) {
        float y = fmaf(cf.b0[k], u, s1[k]);
        s1[k] = fmaf(cf.b1[k], u, fmaf(cf.na1[k], y, s2[k]));
        s2[k] = fmaf(cf.b2[k], u, cf.na2[k] * y);
        u = y;
    }
    return u;
}

__device__ __forceinline__ u64 cascade_step2(u64 u, u64 s1[K], u64 s2[K], const Coef2& cf) {
#pragma unroll
    for (int k = 0; k < K; ++k) {
        u64 y = fma2(cf.b0[k], u, s1[k]);
        s1[k] = fma2(cf.b1[k], u, fma2(cf.na1[k], y, s2[k]));
        s2[k] = fma2(cf.b2[k], u, mul2(cf.na2[k], y));
        u = y;
    }
    return u;
}

extern __shared__ float dyn_smem[];   // 512 rows x ROW floats, interleaved pairs

// stage one tile: chunk c samples [tile*TILE + 4w .. +3] -> row c>>1, pos 8w+2i+(c&1)
__device__ __forceinline__ void stage_tile(const float* __restrict__ xch, int tile, int tid)
{
#pragma unroll
    for (int it = 0; it < 16; ++it) {
        int f = tid + it * THREADS;      // 0..8191
        int c = f >> 3, w = f & 7;
        float4 v = *reinterpret_cast<const float4*>(xch + (size_t)c * CHUNK + tile * TILE + w * 4);
        float* p = dyn_smem + (c >> 1) * ROW + (w << 3) + (c & 1);
        p[0] = v.x; p[2] = v.y; p[4] = v.z; p[6] = v.w;
    }
}

__global__ void __launch_bounds__(THREADS, 1)
iir_cascade_kernel(const float* __restrict__ x,
                   const float* __restrict__ Bs,
                   const float* __restrict__ As,
                   float* __restrict__ yout)
{
    __shared__ float S[THREADS][8];         // pair-aggregate scan array
    __shared__ float Mats[LEVELS][8][8];    // A^(256 * 2^l)
    __shared__ float A128[8][8];            // A^128 (pair combine)
    __shared__ float P[8][8];               // running power of A

    const int ch  = blockIdx.x;
    const int tid = threadIdx.x;

    const float* __restrict__ xch = x + (size_t)ch * LSIG;
    float* __restrict__ ych = yout + (size_t)ch * LSIG;

    // ---- load + normalize coefficients ----
    Coef cf;
    {
        const float* bs = Bs + (size_t)ch * K * 3;
        const float* as = As + (size_t)ch * K * 3;
#pragma unroll
        for (int k = 0; k < K; ++k) {
            float inv = 1.0f / as[k * 3 + 0];
            cf.b0[k]  = bs[k * 3 + 0] * inv;
            cf.b1[k]  = bs[k * 3 + 1] * inv;
            cf.b2[k]  = bs[k * 3 + 2] * inv;
            cf.na1[k] = -(as[k * 3 + 1] * inv);
            cf.na2[k] = -(as[k * 3 + 2] * inv);
        }
    }

    // ---- build state matrix A (warp 0) ----
    if (tid < 8) {
        float t1[K], t2[K];
#pragma unroll
        for (int k = 0; k < K; ++k) {
            t1[k] = (2 * k     == tid) ? 1.f : 0.f;
            t2[k] = (2 * k + 1 == tid) ? 1.f : 0.f;
        }
        cascade_step(0.f, t1, t2, cf);
#pragma unroll
        for (int k = 0; k < K; ++k) {
            P[2 * k][tid]     = t1[k];
            P[2 * k + 1][tid] = t2[k];
        }
    }

    // ---- repeated squaring by warps 0-1 (named barrier; overlaps tile-0 staging
    //      by warps 2-15): A128 = A^(2^7); Mats[it-8] = A^(2^it), it=8..16 ----
    if (tid < 64) {
        const int r = tid >> 3, c = tid & 7;
        asm volatile("bar.sync 1, 64;" ::: "memory");   // P visible to both warps
        for (int it = 1; it <= 16; ++it) {
            float val = 0.f;
#pragma unroll
            for (int kk = 0; kk < 8; ++kk) val = fmaf(P[r][kk], P[kk][c], val);
            asm volatile("bar.sync 1, 64;" ::: "memory");
            P[r][c] = val;
            if (it == 7) A128[r][c] = val;
            if (it >= 8) Mats[it - 8][r][c] = val;
            asm volatile("bar.sync 1, 64;" ::: "memory");
        }
    }

    // ---- broadcast-pack coefficients for f32x2 ----
    Coef2 c2;
#pragma unroll
    for (int k = 0; k < K; ++k) {
        c2.b0[k]  = pk2(cf.b0[k],  cf.b0[k]);
        c2.b1[k]  = pk2(cf.b1[k],  cf.b1[k]);
        c2.b2[k]  = pk2(cf.b2[k],  cf.b2[k]);
        c2.na1[k] = pk2(cf.na1[k], cf.na1[k]);
        c2.na2[k] = pk2(cf.na2[k], cf.na2[k]);
    }

    const u64* __restrict__ rrow =
        reinterpret_cast<const u64*>(dyn_smem + tid * ROW);

    // ================= Pass A: zero-init packed run ===========================
    u64 s1[K] = {0, 0, 0, 0};
    u64 s2[K] = {0, 0, 0, 0};
#pragma unroll 1
    for (int tile = 0; tile < NTILES; ++tile) {
        stage_tile(xch, tile, tid);
        __syncthreads();
#pragma unroll
        for (int j = 0; j < TILE; ++j) {
            cascade_step2(rrow[j], s1, s2, c2);
        }
        __syncthreads();   // reads done before next tile's staging
    }
    float sc_lo[8], sc_hi[8];
#pragma unroll
    for (int k = 0; k < K; ++k) {
        upk2(s1[k], sc_lo[2 * k],     sc_hi[2 * k]);
        upk2(s2[k], sc_lo[2 * k + 1], sc_hi[2 * k + 1]);
    }

    // ---- local pair combine: agg = A128 * sc_lo + sc_hi ----
    float agg[8];
#pragma unroll
    for (int r = 0; r < 8; ++r) {
        float acc = sc_hi[r];
#pragma unroll
        for (int c = 0; c < 8; ++c) acc = fmaf(A128[r][c], sc_lo[c], acc);
        agg[r] = acc;
        S[tid][r] = acc;
    }
    __syncthreads();

    // ---- Kogge-Stone affine scan over 512 pair-aggregates ----
    for (int l = 0; l < LEVELS; ++l) {
        int d = 1 << l;
        float t[8];
        bool act = (tid >= d);
        if (act) {
#pragma unroll
            for (int i = 0; i < 8; ++i) t[i] = S[tid - d][i];
        }
        __syncthreads();
        if (act) {
#pragma unroll
            for (int r = 0; r < 8; ++r) {
                float acc = agg[r];
#pragma unroll
                for (int c = 0; c < 8; ++c) acc = fmaf(Mats[l][r][c], t[c], acc);
                agg[r] = acc;
            }
#pragma unroll
            for (int i = 0; i < 8; ++i) S[tid][i] = agg[i];
        }
        __syncthreads();
    }

    // ---- initial states ----
    float init0[8], init1[8];
    if (tid == 0) {
#pragma unroll
        for (int i = 0; i < 8; ++i) init0[i] = 0.f;
    } else {
#pragma unroll
        for (int i = 0; i < 8; ++i) init0[i] = S[tid - 1][i];
    }
#pragma unroll
    for (int r = 0; r < 8; ++r) {
        float acc = sc_lo[r];
#pragma unroll
        for (int c = 0; c < 8; ++c) acc = fmaf(A128[r][c], init0[c], acc);
        init1[r] = acc;
    }

    // ================= Pass B: rerun from corrected states ====================
#pragma unroll
    for (int k = 0; k < K; ++k) {
        s1[k] = pk2(init0[2 * k],     init1[2 * k]);
        s2[k] = pk2(init0[2 * k + 1], init1[2 * k + 1]);
    }

    u64* __restrict__ wrow = reinterpret_cast<u64*>(dyn_smem + tid * ROW);

#pragma unroll 1
    for (int tile = 0; tile < NTILES; ++tile) {
        __syncthreads();   // prior drain reads (and scan S reads) done
        stage_tile(xch, tile, tid);
        __syncthreads();
        // compute; overwrite row in place with packed outputs
#pragma unroll
        for (int j = 0; j < TILE; ++j) {
            wrow[j] = cascade_step2(wrow[j], s1, s2, c2);
        }
        __syncthreads();   // outputs visible block-wide
        // coalesced drain: gather interleaved -> STG.128
#pragma unroll
        for (int it = 0; it < 16; ++it) {
            int f = tid + it * THREADS;
            int c = f >> 3, w = f & 7;
            const float* p = dyn_smem + (c >> 1) * ROW + (w << 3) + (c & 1);
            float4 v;
            v.x = p[0]; v.y = p[2]; v.z = p[4]; v.w = p[6];
            *reinterpret_cast<float4*>(ych + (size_t)c * CHUNK + tile * TILE + w * 4) = v;
        }
    }
}

extern "C" void kernel_launch(void* const* d_in, const int* in_sizes, int n_in,
                              void* d_out, int out_size)
{
    const float* x  = (const float*)d_in[0];   // (B, C, L) float32
    const float* Bs = (const float*)d_in[1];   // (B, C, K, 3) float32
    const float* As = (const float*)d_in[2];   // (B, C, K, 3) float32
    float* y = (float*)d_out;                  // (B, C, L) float32

    const int dyn_bytes = THREADS * ROW * sizeof(float);   // 135168
    static bool attr_set = false;
    if (!attr_set) {
        cudaFuncSetAttribute(iir_cascade_kernel,
                             cudaFuncAttributeMaxDynamicSharedMemorySize, dyn_bytes);
        attr_set = true;
    }
    iir_cascade_kernel<<<NCH, THREADS, dyn_bytes>>>(x, Bs, As, y);
}